// round 16
// baseline (speedup 1.0000x reference)
#include <cuda_runtime.h>

#define N_NODES 1000000
#define DEGREE 31
#define BLOCK 256
#define THRESH 16
#define TILES ((N_NODES + BLOCK - 1) / BLOCK)   // 3907

__device__ double   g_sum = 0.0;    // re-zeroed by last block each run
__device__ unsigned g_done = 0;

// Single-instruction HW tanh (MUFU.TANH, sm_75+). Max rel error ~2^-11:
// sigmoid via 0.5*tanh(x/2)+0.5 is accurate to ~1e-5 abs — far under the
// 1e-3 correctness gate even after summing 1M nodes (measured 1.4e-7).
__device__ __forceinline__ float tanh_approx(float x) {
    float t;
    asm("tanh.approx.f32 %0, %1;" : "=f"(t) : "f"(x));
    return t;
}

// Per-thread Poisson-binomial DP with absorbing state at THRESH.
// SCHEDULE-SENSITIVE (R7/R8 post-mortems): this exact form, consuming a fully
// materialized pv[] right after the gather, makes ptxas front-batch all 31
// gather LDGs (regs=44, MLP=31, L1~86%). Pruned variants and extra syncs
// before the call re-schedule to pipelined loads and cost +10..110 us.
// Do not restructure.
__device__ __forceinline__ float dp_node(const float* __restrict__ pv) {
    float dp[THRESH + 1];
    dp[0] = 1.0f;
    #pragma unroll
    for (int k = 1; k <= THRESH; k++) dp[k] = 0.0f;

    #pragma unroll
    for (int j = 0; j < DEGREE + 1; j++) {
        const float pj = pv[j];
        const int kmax = (j + 1 < THRESH) ? (j + 1) : THRESH;  // triangular prune
        if (kmax == THRESH)
            dp[THRESH] = fmaf(pj, dp[THRESH - 1], dp[THRESH]); // absorbing state
        #pragma unroll
        for (int k = THRESH - 1; k >= 1; k--)
            if (k <= kmax)
                dp[k] = fmaf(pj, dp[k - 1] - dp[k], dp[k]);
        dp[0] = dp[0] * (1.0f - pj);
    }
    return dp[THRESH];
}

// CONVERGED single fused kernel (R15 verbatim; at the L1tex wavefront floor:
// ~34M wavefronts = 31M random 4B gathers + int4 staging + LDS ~ 117us @NAT).
// Warp-autonomous: each warp detects index dtype locally, stages its 32x31
// indices coalesced into smem, gathers raw gains (4 MB, L2-resident), converts
// with one MUFU.TANH + FMA per value, runs the DP, reduces. No block barrier
// in the hot path; one double atomic per block; last block writes the output.
__global__ void __launch_bounds__(BLOCK) dp_kernel(const float* __restrict__ gains,
                                                   const void* __restrict__ neighbors,
                                                   float* __restrict__ out) {
    __shared__ int   sidx[BLOCK * DEGREE];   // per-warp slices of 32*DEGREE
    __shared__ float sred[BLOCK / 32];

    const int tid  = threadIdx.x;
    const int wid  = tid >> 5;
    const int lane = tid & 31;
    const long long warpStart = (long long)blockIdx.x * BLOCK + wid * 32;

    float contrib = 0.0f;
    if (warpStart < N_NODES) {
        int* sw = sidx + wid * (32 * DEGREE);
        const long long elemBase = warpStart * (long long)DEGREE;

        // Local dtype detection: if int64, hi-words of the first 32 elements
        // are all 0 (indices < 2^20); if int32, those words are uniform random
        // indices in [0, 1e6): P(all 0) ~ 0. L2-hot after the first warp.
        int hi = ((const int*)neighbors)[lane * 2 + 1];
        unsigned all0 = __ballot_sync(0xffffffffu, hi == 0);
        const bool is64 = (all0 == 0xffffffffu);

        // Stage this warp's 32x31 index rows, coalesced + vectorized.
        if (is64) {
            // 992 int64 = 496 int4 (low words at .x and .z).
            const int4* nb4 = (const int4*)((const long long*)neighbors + elemBase);
            #pragma unroll
            for (int t = lane; t < (32 * DEGREE) / 2; t += 32) {
                int4 v = nb4[t];
                sw[2 * t]     = v.x;
                sw[2 * t + 1] = v.z;
            }
        } else {
            // 992 int32 = 248 int4.
            const int4* nb4 = (const int4*)((const int*)neighbors + elemBase);
            #pragma unroll
            for (int t = lane; t < (32 * DEGREE) / 4; t += 32) {
                int4 v = nb4[t];
                sw[4 * t]     = v.x;
                sw[4 * t + 1] = v.y;
                sw[4 * t + 2] = v.z;
                sw[4 * t + 3] = v.w;
            }
        }
        __syncwarp();

        const int node = (int)(warpStart + lane);

        // Batched gather of raw gains (31 independent L2-resident loads).
        float pv[DEGREE + 1];
        pv[0] = gains[node];
        #pragma unroll
        for (int j = 0; j < DEGREE; j++) {
            int idx = sw[lane * DEGREE + j];       // stride 31: bank-conflict-free
            idx = min(max(idx, 0), N_NODES - 1);   // crash-proofing
            pv[j + 1] = __ldg(&gains[idx]);
        }

        // sigmoid(x) = 0.5*tanh(x/2) + 0.5: one MUFU + two FMA-class ops,
        // no dependent RCP chain. Hidden under the L1tex gather shadow.
        #pragma unroll
        for (int j = 0; j < DEGREE + 1; j++)
            pv[j] = fmaf(0.5f, tanh_approx(0.5f * pv[j]), 0.5f);

        contrib = dp_node(pv) - 0.25f * pv[0];
    }

    // Warp reduce -> block reduce -> one double atomic per block.
    #pragma unroll
    for (int o = 16; o; o >>= 1)
        contrib += __shfl_down_sync(0xffffffffu, contrib, o);
    if (lane == 0) sred[wid] = contrib;
    __syncthreads();
    if (tid < 32) {
        float v = (tid < BLOCK / 32) ? sred[tid] : 0.0f;
        #pragma unroll
        for (int o = 4; o; o >>= 1)
            v += __shfl_down_sync(0xffffffffu, v, o);
        if (tid == 0) {
            atomicAdd(&g_sum, (double)v);
            __threadfence();
            unsigned done = atomicAdd(&g_done, 1u);
            if (done == (unsigned)gridDim.x - 1u) {
                double s = atomicAdd(&g_sum, 0.0);   // L2-coherent read
                out[0] = -(float)s;
                g_sum  = 0.0;                         // reset for graph replays
                g_done = 0;
            }
        }
    }
}

extern "C" void kernel_launch(void* const* d_in, const int* in_sizes, int n_in,
                              void* d_out, int out_size) {
    // Resolve input order from element counts (gains: 1M, neighbors: 31M).
    int gi = 0, ni = 1;
    if (in_sizes[0] != N_NODES) { gi = 1; ni = 0; }
    const float* gains     = (const float*)d_in[gi];
    const void*  neighbors = d_in[ni];
    float*       out       = (float*)d_out;

    dp_kernel<<<TILES, BLOCK>>>(gains, neighbors, out);
}

// round 17
// speedup vs baseline: 1.5974x; 1.5974x over previous
#include <cuda_runtime.h>

#define N_NODES 1000000
#define DEGREE 31
#define BLOCK 256
#define THRESH 16
#define TILES ((N_NODES + BLOCK - 1) / BLOCK)   // 3907

__device__ double   g_sum = 0.0;    // re-zeroed by last block each run
__device__ unsigned g_done = 0;

// Single-instruction HW tanh (MUFU.TANH, sm_75+). Max rel error ~2^-11:
// sigmoid via 0.5*tanh(x/2)+0.5 is accurate to ~1e-5 abs — far under the
// 1e-3 correctness gate even after summing 1M nodes (measured 1.4e-7).
__device__ __forceinline__ float tanh_approx(float x) {
    float t;
    asm("tanh.approx.f32 %0, %1;" : "=f"(t) : "f"(x));
    return t;
}

// Per-thread Poisson-binomial DP with absorbing state at THRESH.
// SCHEDULE-SENSITIVE (R7/R8 post-mortems): this exact form, consuming a fully
// materialized pv[] right after the gather, makes ptxas front-batch all 31
// gather LDGs (regs=44, MLP=31, L1~86%). Pruned variants and extra syncs
// before the call re-schedule to pipelined loads and cost +10..110 us.
// Do not restructure.
__device__ __forceinline__ float dp_node(const float* __restrict__ pv) {
    float dp[THRESH + 1];
    dp[0] = 1.0f;
    #pragma unroll
    for (int k = 1; k <= THRESH; k++) dp[k] = 0.0f;

    #pragma unroll
    for (int j = 0; j < DEGREE + 1; j++) {
        const float pj = pv[j];
        const int kmax = (j + 1 < THRESH) ? (j + 1) : THRESH;  // triangular prune
        if (kmax == THRESH)
            dp[THRESH] = fmaf(pj, dp[THRESH - 1], dp[THRESH]); // absorbing state
        #pragma unroll
        for (int k = THRESH - 1; k >= 1; k--)
            if (k <= kmax)
                dp[k] = fmaf(pj, dp[k - 1] - dp[k], dp[k]);
        dp[0] = dp[0] * (1.0f - pj);
    }
    return dp[THRESH];
}

// CONVERGED single fused kernel (R15 verbatim; at the L1tex wavefront floor:
// ~34M wavefronts = 31M random 4B gathers + int4 staging + LDS ~ 117us @ full
// NAT clock). R16's 189us was a uniform 0.61x clock-domain scaling (HBM GB/s
// and duration scaled identically, profile shape unchanged) — environmental,
// not a code property.
// Warp-autonomous: each warp detects index dtype locally, stages its 32x31
// indices coalesced into smem, gathers raw gains (4 MB, L2-resident), converts
// with one MUFU.TANH + FMA per value, runs the DP, reduces. No block barrier
// in the hot path; one double atomic per block; last block writes the output.
__global__ void __launch_bounds__(BLOCK) dp_kernel(const float* __restrict__ gains,
                                                   const void* __restrict__ neighbors,
                                                   float* __restrict__ out) {
    __shared__ int   sidx[BLOCK * DEGREE];   // per-warp slices of 32*DEGREE
    __shared__ float sred[BLOCK / 32];

    const int tid  = threadIdx.x;
    const int wid  = tid >> 5;
    const int lane = tid & 31;
    const long long warpStart = (long long)blockIdx.x * BLOCK + wid * 32;

    float contrib = 0.0f;
    if (warpStart < N_NODES) {
        int* sw = sidx + wid * (32 * DEGREE);
        const long long elemBase = warpStart * (long long)DEGREE;

        // Local dtype detection: if int64, hi-words of the first 32 elements
        // are all 0 (indices < 2^20); if int32, those words are uniform random
        // indices in [0, 1e6): P(all 0) ~ 0. L2-hot after the first warp.
        int hi = ((const int*)neighbors)[lane * 2 + 1];
        unsigned all0 = __ballot_sync(0xffffffffu, hi == 0);
        const bool is64 = (all0 == 0xffffffffu);

        // Stage this warp's 32x31 index rows, coalesced + vectorized.
        if (is64) {
            // 992 int64 = 496 int4 (low words at .x and .z).
            const int4* nb4 = (const int4*)((const long long*)neighbors + elemBase);
            #pragma unroll
            for (int t = lane; t < (32 * DEGREE) / 2; t += 32) {
                int4 v = nb4[t];
                sw[2 * t]     = v.x;
                sw[2 * t + 1] = v.z;
            }
        } else {
            // 992 int32 = 248 int4.
            const int4* nb4 = (const int4*)((const int*)neighbors + elemBase);
            #pragma unroll
            for (int t = lane; t < (32 * DEGREE) / 4; t += 32) {
                int4 v = nb4[t];
                sw[4 * t]     = v.x;
                sw[4 * t + 1] = v.y;
                sw[4 * t + 2] = v.z;
                sw[4 * t + 3] = v.w;
            }
        }
        __syncwarp();

        const int node = (int)(warpStart + lane);

        // Batched gather of raw gains (31 independent L2-resident loads).
        float pv[DEGREE + 1];
        pv[0] = gains[node];
        #pragma unroll
        for (int j = 0; j < DEGREE; j++) {
            int idx = sw[lane * DEGREE + j];       // stride 31: bank-conflict-free
            idx = min(max(idx, 0), N_NODES - 1);   // crash-proofing
            pv[j + 1] = __ldg(&gains[idx]);
        }

        // sigmoid(x) = 0.5*tanh(x/2) + 0.5: one MUFU + two FMA-class ops,
        // no dependent RCP chain. Hidden under the L1tex gather shadow.
        #pragma unroll
        for (int j = 0; j < DEGREE + 1; j++)
            pv[j] = fmaf(0.5f, tanh_approx(0.5f * pv[j]), 0.5f);

        contrib = dp_node(pv) - 0.25f * pv[0];
    }

    // Warp reduce -> block reduce -> one double atomic per block.
    #pragma unroll
    for (int o = 16; o; o >>= 1)
        contrib += __shfl_down_sync(0xffffffffu, contrib, o);
    if (lane == 0) sred[wid] = contrib;
    __syncthreads();
    if (tid < 32) {
        float v = (tid < BLOCK / 32) ? sred[tid] : 0.0f;
        #pragma unroll
        for (int o = 4; o; o >>= 1)
            v += __shfl_down_sync(0xffffffffu, v, o);
        if (tid == 0) {
            atomicAdd(&g_sum, (double)v);
            __threadfence();
            unsigned done = atomicAdd(&g_done, 1u);
            if (done == (unsigned)gridDim.x - 1u) {
                double s = atomicAdd(&g_sum, 0.0);   // L2-coherent read
                out[0] = -(float)s;
                g_sum  = 0.0;                         // reset for graph replays
                g_done = 0;
            }
        }
    }
}

extern "C" void kernel_launch(void* const* d_in, const int* in_sizes, int n_in,
                              void* d_out, int out_size) {
    // Resolve input order from element counts (gains: 1M, neighbors: 31M).
    int gi = 0, ni = 1;
    if (in_sizes[0] != N_NODES) { gi = 1; ni = 0; }
    const float* gains     = (const float*)d_in[gi];
    const void*  neighbors = d_in[ni];
    float*       out       = (float*)d_out;

    dp_kernel<<<TILES, BLOCK>>>(gains, neighbors, out);
}